// round 2
// baseline (speedup 1.0000x reference)
#include <cuda_runtime.h>
#include <cuda_fp16.h>
#include <mma.h>
#include <cstdint>
#include <cstddef>

using namespace nvcuda;

#define NN   16384
#define DF   256
#define KCAT 512

// ---------------- device-global scratch (no allocation allowed) ----------------
__device__ __half g_ftT[(size_t)DF * NN];    // features^T fp16 [256][16384]
__device__ __half g_cat[(size_t)NN * KCAT];  // [features | neigh] fp16 [16384][512]
__device__ __half g_w[(size_t)DF * KCAT];    // W fp16 [256][512]

// ---------------- smem layout (dynamic) ----------------
// A: [2][128][40] half  = 20480 B   @ 0
// B: [2][256][40] half  = 40960 B   @ 20480
// srow: 128 float       =   512 B   @ 61440
// stage (epilogue, reuse): [128][68] float = 34816 B @ 0
constexpr int OFF_B    = 20480;
constexpr int OFF_SROW = 61440;
constexpr int SMEM_BYTES = 61952;
constexpr int AST = 40;   // A/B smem row stride in halves (80 B: LDSM conflict-free)
constexpr int SST = 68;   // stage row stride in floats

__device__ __forceinline__ uint32_t smem_u32(const void* p) {
    uint32_t a;
    asm("{ .reg .u64 t; cvta.to.shared.u64 t, %1; cvt.u32.u64 %0, t; }" : "=r"(a) : "l"(p));
    return a;
}
__device__ __forceinline__ void cpa16(uint32_t saddr, const void* g) {
    asm volatile("cp.async.cg.shared.global [%0], [%1], 16;" :: "r"(saddr), "l"(g));
}
__device__ __forceinline__ void cpa_commit() { asm volatile("cp.async.commit_group;" ::: "memory"); }
__device__ __forceinline__ void cpa_wait0()  { asm volatile("cp.async.wait_group 0;" ::: "memory"); }

// ---------------- prep: features -> g_ftT (transpose, fp16) and g_cat[:, :256] ----------------
__global__ void __launch_bounds__(256) k_prep(const float* __restrict__ f) {
    __shared__ float t[32][33];
    int n0 = blockIdx.x * 32, d0 = blockIdx.y * 32;
    int tx = threadIdx.x, ty = threadIdx.y;
    #pragma unroll
    for (int i = ty; i < 32; i += 8) {
        float v = f[(size_t)(n0 + i) * DF + d0 + tx];
        t[i][tx] = v;
        g_cat[(size_t)(n0 + i) * KCAT + d0 + tx] = __float2half(v);
    }
    __syncthreads();
    #pragma unroll
    for (int i = ty; i < 32; i += 8)
        g_ftT[(size_t)(d0 + i) * NN + n0 + tx] = __float2half(t[tx][i]);
}

// ---------------- prep: W -> fp16 ----------------
__global__ void __launch_bounds__(256) k_wconv(const float* __restrict__ W) {
    int i = blockIdx.x * 256 + threadIdx.x;
    if (i < DF * KCAT) g_w[i] = __float2half(W[i]);
}

// ---------------- shared epilogue: stage -> dst ----------------
// (pass p: warps with wn==p dump acc tiles for cols [p*64, p*64+64), all threads flush)

// ================= kernel: neigh = (adj @ F) / (rowsum+1) -> g_cat[:, 256:512] =================
__global__ void __launch_bounds__(256, 1) k_main(const float* __restrict__ adj) {
    extern __shared__ char sm[];
    __half* Abuf = (__half*)sm;                 // [2][128][40]
    __half* Bbuf = (__half*)(sm + OFF_B);       // [2][256][40]
    float*  srow = (float*)(sm + OFF_SROW);     // [128]
    float*  stage = (float*)sm;                 // [128][68]

    const int tid = threadIdx.x;
    const int lane = tid & 31;
    const int wid = tid >> 5;
    const int wm = wid >> 2, wn = wid & 3;      // 2 x 4 warp grid, 64x64 warp tiles
    const int m0 = blockIdx.x * 128;
    const uint32_t b_u32 = smem_u32(Bbuf);

    wmma::fragment<wmma::accumulator, 16, 16, 16, float> acc[4][4];
    #pragma unroll
    for (int mi = 0; mi < 4; mi++)
        #pragma unroll
        for (int ni = 0; ni < 4; ni++)
            wmma::fill_fragment(acc[mi][ni], 0.0f);

    float rowacc[4] = {0.f, 0.f, 0.f, 0.f};
    float4 va[4];

    // ---- loaders ----
    auto ldgA = [&](int it) {
        int k0 = it * 32;
        #pragma unroll
        for (int j = 0; j < 4; j++) {
            int idx = tid + j * 256;
            int row = idx >> 3, c4 = idx & 7;
            va[j] = *(const float4*)(adj + (size_t)(m0 + row) * NN + k0 + c4 * 4);
        }
    };
    auto stsA = [&](int buf) {
        __half* At = Abuf + buf * 128 * AST;
        #pragma unroll
        for (int j = 0; j < 4; j++) {
            int idx = tid + j * 256;
            int row = idx >> 3, c4 = idx & 7;
            float4 v = va[j];
            rowacc[j] += (v.x + v.y) + (v.z + v.w);
            __half2 h0 = __floats2half2_rn(v.x, v.y);
            __half2 h1 = __floats2half2_rn(v.z, v.w);
            uint2 u;
            u.x = *(uint32_t*)&h0;
            u.y = *(uint32_t*)&h1;
            *(uint2*)(At + row * AST + c4 * 4) = u;
        }
    };
    auto cpaB = [&](int buf, int it) {
        int k0 = it * 32;
        uint32_t b0 = b_u32 + buf * 256 * AST * 2;
        #pragma unroll
        for (int j = 0; j < 4; j++) {
            int idx = tid + j * 256;
            int row = idx >> 2, c8 = idx & 3;
            cpa16(b0 + (row * AST + c8 * 8) * 2, g_ftT + (size_t)row * NN + k0 + c8 * 8);
        }
    };

    // ---- prologue: A(0) in regs, B(0) in flight ----
    ldgA(0);
    cpaB(0, 0);
    cpa_commit();

    constexpr int NK = NN / 32;  // 512
    #pragma unroll 1
    for (int it = 0; it < NK; ++it) {
        int cur = it & 1;
        stsA(cur);                         // A(it) regs -> smem (+rowsum)
        if (it + 1 < NK) ldgA(it + 1);     // prefetch A(it+1), latency hidden by MMA
        cpa_wait0();                       // B(it) arrived
        __syncthreads();                   // A(it) visible; everyone past compute(it-1)
        if (it + 1 < NK) { cpaB(cur ^ 1, it + 1); cpa_commit(); }

        const __half* At = Abuf + cur * 128 * AST;
        const __half* Bt = Bbuf + cur * 256 * AST;
        #pragma unroll
        for (int ks = 0; ks < 2; ++ks) {
            wmma::fragment<wmma::matrix_a, 16, 16, 16, __half, wmma::row_major> af[4];
            #pragma unroll
            for (int mi = 0; mi < 4; mi++)
                wmma::load_matrix_sync(af[mi], At + (wm * 64 + mi * 16) * AST + ks * 16, AST);
            #pragma unroll
            for (int ni = 0; ni < 4; ni++) {
                wmma::fragment<wmma::matrix_b, 16, 16, 16, __half, wmma::col_major> bf;
                wmma::load_matrix_sync(bf, Bt + (wn * 64 + ni * 16) * AST + ks * 16, AST);
                #pragma unroll
                for (int mi = 0; mi < 4; mi++)
                    wmma::mma_sync(acc[mi][ni], af[mi], bf, acc[mi][ni]);
            }
        }
    }

    // ---- rowsum -> 1/(deg+1), deterministic shfl reduce (8 lanes share a row) ----
    #pragma unroll
    for (int j = 0; j < 4; j++) {
        float s = rowacc[j];
        s += __shfl_xor_sync(0xFFFFFFFFu, s, 1);
        s += __shfl_xor_sync(0xFFFFFFFFu, s, 2);
        s += __shfl_xor_sync(0xFFFFFFFFu, s, 4);
        int row = (tid + j * 256) >> 3;
        if ((lane & 7) == 0) srow[row] = 1.0f / (s + 1.0f);
    }
    __syncthreads();  // also fences lagging compute before stage overwrites A/B smem

    // ---- epilogue: 4 passes of 64 columns through fp32 staging ----
    #pragma unroll 1
    for (int p = 0; p < 4; p++) {
        if (wn == p) {
            #pragma unroll
            for (int mi = 0; mi < 4; mi++)
                #pragma unroll
                for (int ni = 0; ni < 4; ni++)
                    wmma::store_matrix_sync(stage + (wm * 64 + mi * 16) * SST + ni * 16,
                                            acc[mi][ni], SST, wmma::mem_row_major);
        }
        __syncthreads();
        #pragma unroll
        for (int j = 0; j < 32; j++) {
            int idx = tid + j * 256;
            int r = idx >> 6, c = idx & 63;
            float v = stage[r * SST + c] * srow[r];
            g_cat[(size_t)(m0 + r) * KCAT + 256 + p * 64 + c] = __float2half(v);
        }
        __syncthreads();
    }
}

// ================= kernel: out = [F|neigh] @ W^T (fp16, K=512) =================
__global__ void __launch_bounds__(256, 1) k_out(float* __restrict__ out) {
    extern __shared__ char sm[];
    __half* Abuf = (__half*)sm;
    __half* Bbuf = (__half*)(sm + OFF_B);
    float*  stage = (float*)sm;

    const int tid = threadIdx.x;
    const int wid = tid >> 5;
    const int wm = wid >> 2, wn = wid & 3;
    const int m0 = blockIdx.x * 128;
    const uint32_t a_u32 = smem_u32(Abuf);
    const uint32_t b_u32 = smem_u32(Bbuf);

    wmma::fragment<wmma::accumulator, 16, 16, 16, float> acc[4][4];
    #pragma unroll
    for (int mi = 0; mi < 4; mi++)
        #pragma unroll
        for (int ni = 0; ni < 4; ni++)
            wmma::fill_fragment(acc[mi][ni], 0.0f);

    auto loadTile = [&](int buf, int it) {
        int k0 = it * 32;
        uint32_t a0 = a_u32 + buf * 128 * AST * 2;
        uint32_t b0 = b_u32 + buf * 256 * AST * 2;
        #pragma unroll
        for (int j = 0; j < 2; j++) {    // A: 128 rows x 4 chunks = 512
            int idx = tid + j * 256;
            int row = idx >> 2, c8 = idx & 3;
            cpa16(a0 + (row * AST + c8 * 8) * 2, g_cat + (size_t)(m0 + row) * KCAT + k0 + c8 * 8);
        }
        #pragma unroll
        for (int j = 0; j < 4; j++) {    // B: 256 rows x 4 chunks = 1024
            int idx = tid + j * 256;
            int row = idx >> 2, c8 = idx & 3;
            cpa16(b0 + (row * AST + c8 * 8) * 2, g_w + (size_t)row * KCAT + k0 + c8 * 8);
        }
    };

    loadTile(0, 0);
    cpa_commit();

    constexpr int NK = KCAT / 32;  // 16
    #pragma unroll 1
    for (int it = 0; it < NK; ++it) {
        int cur = it & 1;
        cpa_wait0();
        __syncthreads();
        if (it + 1 < NK) { loadTile(cur ^ 1, it + 1); cpa_commit(); }

        const __half* At = Abuf + cur * 128 * AST;
        const __half* Bt = Bbuf + cur * 256 * AST;
        #pragma unroll
        for (int ks = 0; ks < 2; ++ks) {
            wmma::fragment<wmma::matrix_a, 16, 16, 16, __half, wmma::row_major> af[4];
            #pragma unroll
            for (int mi = 0; mi < 4; mi++)
                wmma::load_matrix_sync(af[mi], At + (wm * 64 + mi * 16) * AST + ks * 16, AST);
            #pragma unroll
            for (int ni = 0; ni < 4; ni++) {
                wmma::fragment<wmma::matrix_b, 16, 16, 16, __half, wmma::col_major> bf;
                wmma::load_matrix_sync(bf, Bt + (wn * 64 + ni * 16) * AST + ks * 16, AST);
                #pragma unroll
                for (int mi = 0; mi < 4; mi++)
                    wmma::mma_sync(acc[mi][ni], af[mi], bf, acc[mi][ni]);
            }
        }
        __syncthreads();
    }

    #pragma unroll 1
    for (int p = 0; p < 4; p++) {
        if (wn == p) {
            #pragma unroll
            for (int mi = 0; mi < 4; mi++)
                #pragma unroll
                for (int ni = 0; ni < 4; ni++)
                    wmma::store_matrix_sync(stage + (wm * 64 + mi * 16) * SST + ni * 16,
                                            acc[mi][ni], SST, wmma::mem_row_major);
        }
        __syncthreads();
        #pragma unroll
        for (int j = 0; j < 32; j++) {
            int idx = tid + j * 256;
            int r = idx >> 6, c = idx & 63;
            out[(size_t)(m0 + r) * DF + p * 64 + c] = stage[r * SST + c];
        }
        __syncthreads();
    }
}

// ---------------- launch ----------------
extern "C" void kernel_launch(void* const* d_in, const int* in_sizes, int n_in,
                              void* d_out, int out_size) {
    // route inputs by element count (robust to metadata order)
    const float* features = nullptr;
    const float* adj = nullptr;
    const float* W = nullptr;
    for (int i = 0; i < n_in; i++) {
        if (in_sizes[i] == NN * NN) adj = (const float*)d_in[i];
        else if (in_sizes[i] == NN * DF) features = (const float*)d_in[i];
        else if (in_sizes[i] == DF * KCAT) W = (const float*)d_in[i];
    }
    float* out = (float*)d_out;

    cudaFuncSetAttribute(k_main, cudaFuncAttributeMaxDynamicSharedMemorySize, SMEM_BYTES);
    cudaFuncSetAttribute(k_out,  cudaFuncAttributeMaxDynamicSharedMemorySize, SMEM_BYTES);

    k_prep<<<dim3(NN / 32, DF / 32), dim3(32, 8)>>>(features);
    k_wconv<<<(DF * KCAT + 255) / 256, 256>>>(W);
    k_main<<<NN / 128, 256, SMEM_BYTES>>>(adj);
    k_out<<<NN / 128, 256, SMEM_BYTES>>>(out);
}